// round 15
// baseline (speedup 1.0000x reference)
#include <cuda_runtime.h>
#include <cstdint>
#include <math.h>

// ---------------------------------------------------------------------------
// Problem constants: B=128, T=1024, D=512, H=512, 4H=2048
//   0: sequence_tensor f32 [128,1024,512]
//   1: batch_lengths   int32 (JAX x64 off) or int64 [128], sorted descending
//   2: W_ih f32 [2048,512]   3: W_hh f32 [2048,512]
//   4: b_ih f32 [2048]       5: b_hh f32 [2048]
// Output: concat( out[128,1024,512], h_final[1,128,512], c_final[1,128,512] )
//
// NOTE: harness lowers PTX through compute_103 (non-'a') -> tcgen05 is
// UNAVAILABLE (ptxas rejects it).  FFMA2 roofline is the ceiling.
// ---------------------------------------------------------------------------

#define Bsz   128
#define Tsz   1024
#define Dsz   512
#define Hsz   512
#define G4    2048
#define PPITCH 68

// G stored TRANSPOSED: G[t][j][b] -> phase-1 stores and phase-2 prefetch
// are both warp-coalesced.
__device__ float g_G[(size_t)Tsz * G4 * Bsz];
__device__ float g_hbuf[2][Bsz * Hsz];
// init-only atomic barrier state + per-step flag array (1 line per btile)
__device__ __align__(128) unsigned g_bar_cnt4[4][32];
__device__ __align__(128) unsigned g_bar_gen4[4][32];
__device__ __align__(128) unsigned g_flag4[4][32];

// ---- packed fp32 helpers (FFMA2 via PTX fma.rn.f32x2) -----------------------
__device__ __forceinline__ unsigned long long pack2(float x, float y) {
    unsigned long long r;
    asm("mov.b64 %0, {%1, %2};" : "=l"(r) : "f"(x), "f"(y));
    return r;
}
__device__ __forceinline__ void unpack2(unsigned long long v, float& x, float& y) {
    asm("mov.b64 {%0, %1}, %2;" : "=f"(x), "=f"(y) : "l"(v));
}
#define FMA2(d, a, b) asm("fma.rn.f32x2 %0, %1, %2, %0;" : "+l"(d) : "l"(a), "l"(b))

// ---- scoped atomics / release-acquire ----------------------------------------
__device__ __forceinline__ unsigned ld_acquire_gpu(unsigned* p) {
    unsigned v;
    asm volatile("ld.acquire.gpu.u32 %0, [%1];" : "=r"(v) : "l"(p) : "memory");
    return v;
}
__device__ __forceinline__ unsigned ld_relaxed_gpu(unsigned* p) {
    unsigned v;
    asm volatile("ld.relaxed.gpu.u32 %0, [%1];" : "=r"(v) : "l"(p) : "memory");
    return v;
}
__device__ __forceinline__ unsigned atom_add_acqrel_gpu(unsigned* p, unsigned v) {
    unsigned o;
    asm volatile("atom.add.acq_rel.gpu.u32 %0, [%1], %2;"
                 : "=r"(o) : "l"(p), "r"(v) : "memory");
    return o;
}
__device__ __forceinline__ void st_release_gpu(unsigned* p, unsigned v) {
    asm volatile("st.release.gpu.u32 [%0], %1;" :: "l"(p), "r"(v) : "memory");
}
__device__ __forceinline__ void st_relaxed_gpu(unsigned* p, unsigned v) {
    asm volatile("st.relaxed.gpu.u32 [%0], %1;" :: "l"(p), "r"(v) : "memory");
}

// ---- length dtype detection --------------------------------------------------
__device__ __forceinline__ bool lens_is64(const int* p) {
    return (p[1] == 0 && p[3] == 0 && p[5] == 0);
}
__device__ __forceinline__ int load_len(const int* p, bool is64, int b) {
    return is64 ? p[2 * b] : p[b];
}

// ---------------------------------------------------------------------------
// Phase 1: G[t][j][b] = sum_k W_ih[j][k] * seq[b][t][k] + bias[j]
// 128x128x16 SGEMM per block, FFMA2, now with a DOUBLE-BUFFERED k-pipeline:
// chunk c+1 is LDG'd into registers during compute of chunk c and STS'd into
// the alternate buffer -> ONE __syncthreads per chunk (was 2), FMA pipe never
// drains against LDG latency.
// ---------------------------------------------------------------------------
__global__ void __launch_bounds__(256) pregemm_kernel(
    const float* __restrict__ seq,
    const float* __restrict__ Wih,
    const float* __restrict__ bih,
    const float* __restrict__ bhh,
    const int*   __restrict__ lensraw)
{
    __shared__ float As[2][16][128];
    __shared__ float Bs[2][16][128];

    const int t   = blockIdx.y;
    const int j0  = blockIdx.x * 128;
    const int tid = threadIdx.x;
    const int tx  = tid & 15;            // batch col group (8 b)
    const int ty  = tid >> 4;            // gate row group (8 j)

    const bool is64 = lens_is64(lensraw);
    const bool grpActive = (load_len(lensraw, is64, tx * 8) > t);

    // acc2[i][p]: packed batch pair (b = tx*8 + 2p, +1) for gate row i
    unsigned long long acc2[8][4];
#pragma unroll
    for (int i = 0; i < 8; ++i) {
        const int j = j0 + ty * 8 + i;
        const float bv = bih[j] + bhh[j];
        const unsigned long long bb = pack2(bv, bv);
#pragma unroll
        for (int p = 0; p < 4; ++p) acc2[i][p] = bb;
    }

    const int lm = tid >> 1;
    const int lk = (tid & 1) * 8;
    const float* arow = Wih + (size_t)(j0 + lm) * Dsz + lk;          // gates
    const float* brow = seq + ((size_t)lm * Tsz + t) * Dsz + lk;     // batch

    float4 fa0 = *(const float4*)(arow);
    float4 fa1 = *(const float4*)(arow + 4);
    float4 fb0 = *(const float4*)(brow);
    float4 fb1 = *(const float4*)(brow + 4);

#define STS_FRAG(B) do {                                                     \
    As[B][lk + 0][lm] = fa0.x; As[B][lk + 1][lm] = fa0.y;                    \
    As[B][lk + 2][lm] = fa0.z; As[B][lk + 3][lm] = fa0.w;                    \
    As[B][lk + 4][lm] = fa1.x; As[B][lk + 5][lm] = fa1.y;                    \
    As[B][lk + 6][lm] = fa1.z; As[B][lk + 7][lm] = fa1.w;                    \
    Bs[B][lk + 0][lm] = fb0.x; Bs[B][lk + 1][lm] = fb0.y;                    \
    Bs[B][lk + 2][lm] = fb0.z; Bs[B][lk + 3][lm] = fb0.w;                    \
    Bs[B][lk + 4][lm] = fb1.x; Bs[B][lk + 5][lm] = fb1.y;                    \
    Bs[B][lk + 6][lm] = fb1.z; Bs[B][lk + 7][lm] = fb1.w;                    \
} while (0)

    STS_FRAG(0);

#pragma unroll 1
    for (int c = 0; c < 32; ++c) {
        __syncthreads();                  // buf[c&1] ready for everyone
        const int buf = c & 1;
        if (c < 31) {                     // prefetch chunk c+1 into registers
            const int k0 = (c + 1) * 16;
            fa0 = *(const float4*)(arow + k0);
            fa1 = *(const float4*)(arow + k0 + 4);
            fb0 = *(const float4*)(brow + k0);
            fb1 = *(const float4*)(brow + k0 + 4);
        }
        if (grpActive) {
#pragma unroll
            for (int kk = 0; kk < 16; ++kk) {
                const float4 a0 = *(const float4*)&As[buf][kk][ty * 8];
                const float4 a1 = *(const float4*)&As[buf][kk][ty * 8 + 4];
                const ulonglong2 bb0 = *(const ulonglong2*)&Bs[buf][kk][tx * 8];
                const ulonglong2 bb1 = *(const ulonglong2*)&Bs[buf][kk][tx * 8 + 4];
                const float a[8] = {a0.x, a0.y, a0.z, a0.w,
                                    a1.x, a1.y, a1.z, a1.w};
#pragma unroll
                for (int i = 0; i < 8; ++i) {
                    const unsigned long long ad = pack2(a[i], a[i]);
                    FMA2(acc2[i][0], ad, bb0.x);
                    FMA2(acc2[i][1], ad, bb0.y);
                    FMA2(acc2[i][2], ad, bb1.x);
                    FMA2(acc2[i][3], ad, bb1.y);
                }
            }
        }
        if (c < 31) {                     // stage c+1 into the other buffer
            if (buf == 0) { STS_FRAG(1); } else { STS_FRAG(0); }
        }
    }
#undef STS_FRAG

    if (grpActive) {
        float* Gt = g_G + ((size_t)t << 18);     // 2048*128 = 1<<18
#pragma unroll
        for (int i = 0; i < 8; ++i) {
            float f0, f1, f2, f3, f4, f5, f6, f7;
            unpack2(acc2[i][0], f0, f1);
            unpack2(acc2[i][1], f2, f3);
            unpack2(acc2[i][2], f4, f5);
            unpack2(acc2[i][3], f6, f7);
            const size_t o = (size_t)(j0 + ty * 8 + i) * Bsz + tx * 8;
            *(float4*)&Gt[o]     = make_float4(f0, f1, f2, f3);
            *(float4*)&Gt[o + 4] = make_float4(f4, f5, f6, f7);
        }
    }
}

// =============================================================================
// Barriers.
//  - tile_barrier: atomic cnt/gen barrier, used ONCE at kernel start
//    (replay-safe; also publishes the flag-array zeroing).
//  - flag_barrier: steady-state per-step barrier with NO atomic contention:
//    each block st.release's its own slot (value = t+1, monotonic within the
//    launch); threads 0..31 spin on the 32 slots (one coalesced 128B line).
// =============================================================================
__device__ __forceinline__ void tile_barrier(unsigned* cnt, unsigned* gen)
{
    __syncthreads();
    if (threadIdx.x == 0) {
        const unsigned old = ld_relaxed_gpu(gen);
        const unsigned ticket = atom_add_acqrel_gpu(cnt, 1u);
        if (ticket == 31u) {
            st_relaxed_gpu(cnt, 0u);
            st_release_gpu(gen, old + 1u);
        } else {
            while (ld_acquire_gpu(gen) == old) { }
        }
    }
    __syncthreads();
}

__device__ __forceinline__ void flag_barrier(unsigned* flags, int slot, unsigned val)
{
    __syncthreads();                       // all block stores done
    const int tid = threadIdx.x;
    if (tid == 0) st_release_gpu(&flags[slot], val);   // publish arrival
    if (tid < 32) {
        while (ld_acquire_gpu(&flags[tid]) < val) { }  // wait all 32 blocks
    }
    __syncthreads();                       // publish acquire to whole block
}

__device__ __forceinline__ float sigmf(float x) {
    return __fdividef(1.f, 1.f + __expf(-x));
}
__device__ __forceinline__ float tanh_fast(float x) {
    return 1.f - __fdividef(2.f, __expf(2.f * x) + 1.f);
}

// =============================================================================
// Phase 2: persistent recurrence (round-14 structure; flag barriers).
// 128 blocks = (btile 0..3 [32 rows]) x (ntile 0..31 [16 units]), 512 thr.
// =============================================================================
__global__ void __launch_bounds__(512, 1) lstm_steps_kernel(
    const float* __restrict__ Whh,
    const int*   __restrict__ lensraw,
    float* __restrict__ out,    // [B,T,H]
    float* __restrict__ hfin,   // [B,H]
    float* __restrict__ cfin)   // [B,H]
{
    extern __shared__ float sm[];
    float* W_s = sm;                       // [512][64]
    float* h_s = sm + 512 * 64;            // [512][32]
    float* P_s = sm + 512 * 64 + 512 * 32; // [4][32][PPITCH]

    const int tid   = threadIdx.x;
    const int bx    = blockIdx.x;
    const int ntile = bx & 31;
    const int btile = bx >> 5;
    const int n0    = ntile * 16;
    const int b0    = btile * 32;
    unsigned* bar_cnt = &g_bar_cnt4[btile][0];
    unsigned* bar_gen = &g_bar_gen4[btile][0];
    unsigned* flags   = &g_flag4[btile][0];

    // ---- stage W_hh (once): W_s[k][nh*4+gate] = Whh[gate*512 + n0+nh][k]
    {
        const int c     = tid >> 3;
        const int chunk = tid & 7;
        const int gate  = c & 3;
        const int nh    = c >> 2;
        const float* wrow = Whh + (size_t)(gate * Hsz + n0 + nh) * Hsz;
        for (int k = chunk * 64; k < chunk * 64 + 64; k += 4) {
            const float4 v = *(const float4*)(wrow + k);
            W_s[(k + 0) * 64 + c] = v.x;
            W_s[(k + 1) * 64 + c] = v.y;
            W_s[(k + 2) * 64 + c] = v.z;
            W_s[(k + 3) * 64 + c] = v.w;
        }
    }
    // ---- zero this block's slice of hbuf[0] and its barrier flag
    {
        const int r = tid >> 4, cc = tid & 15;
        g_hbuf[0][(size_t)(b0 + r) * Hsz + n0 + cc] = 0.f;
        if (tid == 0) st_relaxed_gpu(&flags[ntile], 0u);
    }
    // ---- zero-fill out for this btile
    {
        const float4 z4 = make_float4(0.f, 0.f, 0.f, 0.f);
        for (int it = 0; it < 256; ++it) {
            const int idx = it * 512 + tid;
            const int bt  = idx >> 7;
            const int f4  = idx & 127;
            const int r   = bt >> 5;
            const int tt  = ntile * 32 + (bt & 31);
            float4* dst = (float4*)(out + ((size_t)(b0 + r) * Tsz + tt) * Hsz);
            dst[f4] = z4;
        }
    }
    tile_barrier(bar_cnt, bar_gen);   // one-time init barrier (replay-safe)

    // ---- GEMM mapping
    const int cg = tid & 31;
    const int rg = (tid >> 5) & 3;
    const int kq = tid >> 7;
    const float* wbase = W_s + 2 * cg;
    const float* hbase = h_s + rg * 8;
    float* Pk = P_s + kq * (32 * PPITCH);

    // ---- epilogue mapping: one (row, unit) per thread
    const int er = tid & 31;
    const int un = tid >> 5;
    const int eb = b0 + er;
    const int n  = n0 + un;

    const bool is64 = lens_is64(lensraw);
    const int len_tile = load_len(lensraw, is64, b0);
    const int len_r    = load_len(lensraw, is64, eb);

    float hprev = 0.f, creg = 0.f;

    const int st_b  = tid & 31;
    const int st_kc = tid >> 5;

#pragma unroll 1
    for (int t = 0; t < Tsz; ++t) {
        float* hnext = g_hbuf[(t + 1) & 1];
        const bool tileActive = (t < len_tile);

        if (tileActive) {
            // -- prefetch G[t] (coalesced: lanes = consecutive b)
            const float* grb = g_G + ((size_t)t << 18) + (size_t)n * Bsz + eb;
            const float gi = __ldcg(grb);
            const float gf = __ldcg(grb + 512 * Bsz);
            const float gg = __ldcg(grb + 1024 * Bsz);
            const float go = __ldcg(grb + 1536 * Bsz);

            // -- stage h tile: h_s[k][b]
            {
                const float* src = g_hbuf[t & 1] +
                                   (size_t)(b0 + st_b) * Hsz + st_kc * 32;
#pragma unroll
                for (int i = 0; i < 8; ++i) {
                    const float4 v = __ldcg((const float4*)(src + i * 4));
                    const int k = st_kc * 32 + i * 4;
                    h_s[(k + 0) * 32 + st_b] = v.x;
                    h_s[(k + 1) * 32 + st_b] = v.y;
                    h_s[(k + 2) * 32 + st_b] = v.z;
                    h_s[(k + 3) * 32 + st_b] = v.w;
                }
            }
            __syncthreads();

            // -- micro-GEMM over this thread's k quarter (8 rows x 2 cols)
            unsigned long long A00 = 0ull, A01 = 0ull;
            unsigned long long A10 = 0ull, A11 = 0ull;
            unsigned long long A20 = 0ull, A21 = 0ull;
            unsigned long long A30 = 0ull, A31 = 0ull;
            const int kend = kq * 128 + 128;
#pragma unroll 8
            for (int k = kq * 128; k < kend; ++k) {
                const float2 wv = *(const float2*)(wbase + k * 64);
                const ulonglong2 hA = *(const ulonglong2*)(hbase + k * 32);
                const ulonglong2 hB = *(const ulonglong2*)(hbase + k * 32 + 4);
                const unsigned long long w0 = pack2(wv.x, wv.x);
                const unsigned long long w1 = pack2(wv.y, wv.y);
                FMA2(A00, hA.x, w0); FMA2(A01, hA.x, w1);
                FMA2(A10, hA.y, w0); FMA2(A11, hA.y, w1);
                FMA2(A20, hB.x, w0); FMA2(A21, hB.x, w1);
                FMA2(A30, hB.y, w0); FMA2(A31, hB.y, w1);
            }
            {
                float e0, o0, e1, o1;
                const int rb = rg * 8;
                float2* pr;
                unpack2(A00, e0, o0); unpack2(A01, e1, o1);
                pr = (float2*)&Pk[(rb+0)*PPITCH + 2*cg]; *pr = make_float2(e0, e1);
                pr = (float2*)&Pk[(rb+1)*PPITCH + 2*cg]; *pr = make_float2(o0, o1);
                unpack2(A10, e0, o0); unpack2(A11, e1, o1);
                pr = (float2*)&Pk[(rb+2)*PPITCH + 2*cg]; *pr = make_float2(e0, e1);
                pr = (float2*)&Pk[(rb+3)*PPITCH + 2*cg]; *pr = make_float2(o0, o1);
                unpack2(A20, e0, o0); unpack2(A21, e1, o1);
                pr = (float2*)&Pk[(rb+4)*PPITCH + 2*cg]; *pr = make_float2(e0, e1);
                pr = (float2*)&Pk[(rb+5)*PPITCH + 2*cg]; *pr = make_float2(o0, o1);
                unpack2(A30, e0, o0); unpack2(A31, e1, o1);
                pr = (float2*)&Pk[(rb+6)*PPITCH + 2*cg]; *pr = make_float2(e0, e1);
                pr = (float2*)&Pk[(rb+7)*PPITCH + 2*cg]; *pr = make_float2(o0, o1);
            }
            __syncthreads();

            // -- epilogue: reduce 4 k-quarters, add G, LSTM update
            {
                const float4 p0 = *(const float4*)&P_s[0*32*PPITCH + er*PPITCH + un*4];
                const float4 p1 = *(const float4*)&P_s[1*32*PPITCH + er*PPITCH + un*4];
                const float4 p2 = *(const float4*)&P_s[2*32*PPITCH + er*PPITCH + un*4];
                const float4 p3 = *(const float4*)&P_s[3*32*PPITCH + er*PPITCH + un*4];
                const float ai = (p0.x + p1.x) + (p2.x + p3.x);
                const float af = (p0.y + p1.y) + (p2.y + p3.y);
                const float ag = (p0.z + p1.z) + (p2.z + p3.z);
                const float ao = (p0.w + p1.w) + (p2.w + p3.w);
                const float iv = sigmf(ai + gi);
                const float fv = sigmf(af + gf);
                const float gv = tanh_fast(ag + gg);
                const float ov = sigmf(ao + go);
                const float cn = fv * creg + iv * gv;
                const float hn = ov * tanh_fast(cn);
                const bool act = (t < len_r);
                creg  = act ? cn : creg;
                hprev = act ? hn : hprev;
                if (act) out[((size_t)eb * Tsz + t) * Hsz + n] = hn;
                hnext[(size_t)eb * Hsz + n] = hprev;
            }
        }
        flag_barrier(flags, ntile, (unsigned)(t + 1));   // h handoff
    }

    hfin[(size_t)eb * Hsz + n] = hprev;
    cfin[(size_t)eb * Hsz + n] = creg;
}

// ---------------------------------------------------------------------------
extern "C" void kernel_launch(void* const* d_in, const int* in_sizes, int n_in,
                              void* d_out, int out_size)
{
    (void)in_sizes; (void)n_in; (void)out_size;
    const float* seq  = (const float*)d_in[0];
    const int*   lens = (const int*)d_in[1];
    const float* Wih  = (const float*)d_in[2];
    const float* Whh  = (const float*)d_in[3];
    const float* bih  = (const float*)d_in[4];
    const float* bhh  = (const float*)d_in[5];

    float* outp = (float*)d_out;
    float* hfin = outp + (size_t)Bsz * Tsz * Hsz;
    float* cfin = hfin + (size_t)Bsz * Hsz;

    const int smem2 = (512 * 64 + 512 * 32 + 4 * 32 * PPITCH) * 4;
    cudaFuncSetAttribute(lstm_steps_kernel,
                         cudaFuncAttributeMaxDynamicSharedMemorySize, smem2);

    // Phase 1: input-gate GEMM (double-buffered) -> transposed G[t][j][b]
    dim3 grid1(G4 / 128, Tsz);
    pregemm_kernel<<<grid1, 256>>>(seq, Wih, bih, bhh, lens);

    // Phase 2: persistent recurrence (128 co-resident blocks, flag barriers)
    lstm_steps_kernel<<<128, 512, smem2>>>(Whh, lens, outp, hfin, cfin);
}

// round 16
// speedup vs baseline: 1.3173x; 1.3173x over previous
#include <cuda_runtime.h>
#include <cstdint>
#include <math.h>

// ---------------------------------------------------------------------------
// Problem constants: B=128, T=1024, D=512, H=512, 4H=2048
//   0: sequence_tensor f32 [128,1024,512]
//   1: batch_lengths   int32 (JAX x64 off) or int64 [128], sorted descending
//   2: W_ih f32 [2048,512]   3: W_hh f32 [2048,512]
//   4: b_ih f32 [2048]       5: b_hh f32 [2048]
// Output: concat( out[128,1024,512], h_final[1,128,512], c_final[1,128,512] )
//
// NOTE: harness lowers PTX through compute_103 (non-'a') -> tcgen05 is
// UNAVAILABLE (ptxas rejects it).  FFMA2 roofline is the ceiling.
//
// Round-16 composition of best-measured parts:
//   phase 1: round-15 double-buffered FFMA2 SGEMM  (~3.4 ms, confirmed win)
//   phase 2: round-14 recurrence w/ atomic tile_barrier (13.8 us/step best)
// ---------------------------------------------------------------------------

#define Bsz   128
#define Tsz   1024
#define Dsz   512
#define Hsz   512
#define G4    2048
#define PPITCH 68

// G stored TRANSPOSED: G[t][j][b] -> phase-1 stores and phase-2 prefetch
// are both warp-coalesced.
__device__ float g_G[(size_t)Tsz * G4 * Bsz];
__device__ float g_hbuf[2][Bsz * Hsz];
__device__ __align__(128) unsigned g_bar_cnt4[4][32];
__device__ __align__(128) unsigned g_bar_gen4[4][32];

// ---- packed fp32 helpers (FFMA2 via PTX fma.rn.f32x2) -----------------------
__device__ __forceinline__ unsigned long long pack2(float x, float y) {
    unsigned long long r;
    asm("mov.b64 %0, {%1, %2};" : "=l"(r) : "f"(x), "f"(y));
    return r;
}
__device__ __forceinline__ void unpack2(unsigned long long v, float& x, float& y) {
    asm("mov.b64 {%0, %1}, %2;" : "=f"(x), "=f"(y) : "l"(v));
}
#define FMA2(d, a, b) asm("fma.rn.f32x2 %0, %1, %2, %0;" : "+l"(d) : "l"(a), "l"(b))

// ---- scoped atomics / release-acquire ----------------------------------------
__device__ __forceinline__ unsigned ld_acquire_gpu(unsigned* p) {
    unsigned v;
    asm volatile("ld.acquire.gpu.u32 %0, [%1];" : "=r"(v) : "l"(p) : "memory");
    return v;
}
__device__ __forceinline__ unsigned ld_relaxed_gpu(unsigned* p) {
    unsigned v;
    asm volatile("ld.relaxed.gpu.u32 %0, [%1];" : "=r"(v) : "l"(p) : "memory");
    return v;
}
__device__ __forceinline__ unsigned atom_add_acqrel_gpu(unsigned* p, unsigned v) {
    unsigned o;
    asm volatile("atom.add.acq_rel.gpu.u32 %0, [%1], %2;"
                 : "=r"(o) : "l"(p), "r"(v) : "memory");
    return o;
}
__device__ __forceinline__ void st_release_gpu(unsigned* p, unsigned v) {
    asm volatile("st.release.gpu.u32 [%0], %1;" :: "l"(p), "r"(v) : "memory");
}
__device__ __forceinline__ void st_relaxed_gpu(unsigned* p, unsigned v) {
    asm volatile("st.relaxed.gpu.u32 [%0], %1;" :: "l"(p), "r"(v) : "memory");
}

// ---- length dtype detection --------------------------------------------------
__device__ __forceinline__ bool lens_is64(const int* p) {
    return (p[1] == 0 && p[3] == 0 && p[5] == 0);
}
__device__ __forceinline__ int load_len(const int* p, bool is64, int b) {
    return is64 ? p[2 * b] : p[b];
}

// ---------------------------------------------------------------------------
// Phase 1: G[t][j][b] = sum_k W_ih[j][k] * seq[b][t][k] + bias[j]
// 128x128x16 SGEMM per block, FFMA2, double-buffered k-pipeline:
// chunk c+1 is LDG'd into registers during compute of chunk c and STS'd into
// the alternate buffer -> ONE __syncthreads per chunk.
// ---------------------------------------------------------------------------
__global__ void __launch_bounds__(256) pregemm_kernel(
    const float* __restrict__ seq,
    const float* __restrict__ Wih,
    const float* __restrict__ bih,
    const float* __restrict__ bhh,
    const int*   __restrict__ lensraw)
{
    __shared__ float As[2][16][128];
    __shared__ float Bs[2][16][128];

    const int t   = blockIdx.y;
    const int j0  = blockIdx.x * 128;
    const int tid = threadIdx.x;
    const int tx  = tid & 15;            // batch col group (8 b)
    const int ty  = tid >> 4;            // gate row group (8 j)

    const bool is64 = lens_is64(lensraw);
    const bool grpActive = (load_len(lensraw, is64, tx * 8) > t);

    // acc2[i][p]: packed batch pair (b = tx*8 + 2p, +1) for gate row i
    unsigned long long acc2[8][4];
#pragma unroll
    for (int i = 0; i < 8; ++i) {
        const int j = j0 + ty * 8 + i;
        const float bv = bih[j] + bhh[j];
        const unsigned long long bb = pack2(bv, bv);
#pragma unroll
        for (int p = 0; p < 4; ++p) acc2[i][p] = bb;
    }

    const int lm = tid >> 1;
    const int lk = (tid & 1) * 8;
    const float* arow = Wih + (size_t)(j0 + lm) * Dsz + lk;          // gates
    const float* brow = seq + ((size_t)lm * Tsz + t) * Dsz + lk;     // batch

    float4 fa0 = *(const float4*)(arow);
    float4 fa1 = *(const float4*)(arow + 4);
    float4 fb0 = *(const float4*)(brow);
    float4 fb1 = *(const float4*)(brow + 4);

#define STS_FRAG(B) do {                                                     \
    As[B][lk + 0][lm] = fa0.x; As[B][lk + 1][lm] = fa0.y;                    \
    As[B][lk + 2][lm] = fa0.z; As[B][lk + 3][lm] = fa0.w;                    \
    As[B][lk + 4][lm] = fa1.x; As[B][lk + 5][lm] = fa1.y;                    \
    As[B][lk + 6][lm] = fa1.z; As[B][lk + 7][lm] = fa1.w;                    \
    Bs[B][lk + 0][lm] = fb0.x; Bs[B][lk + 1][lm] = fb0.y;                    \
    Bs[B][lk + 2][lm] = fb0.z; Bs[B][lk + 3][lm] = fb0.w;                    \
    Bs[B][lk + 4][lm] = fb1.x; Bs[B][lk + 5][lm] = fb1.y;                    \
    Bs[B][lk + 6][lm] = fb1.z; Bs[B][lk + 7][lm] = fb1.w;                    \
} while (0)

    STS_FRAG(0);

#pragma unroll 1
    for (int c = 0; c < 32; ++c) {
        __syncthreads();                  // buf[c&1] ready for everyone
        const int buf = c & 1;
        if (c < 31) {                     // prefetch chunk c+1 into registers
            const int k0 = (c + 1) * 16;
            fa0 = *(const float4*)(arow + k0);
            fa1 = *(const float4*)(arow + k0 + 4);
            fb0 = *(const float4*)(brow + k0);
            fb1 = *(const float4*)(brow + k0 + 4);
        }
        if (grpActive) {
#pragma unroll
            for (int kk = 0; kk < 16; ++kk) {
                const float4 a0 = *(const float4*)&As[buf][kk][ty * 8];
                const float4 a1 = *(const float4*)&As[buf][kk][ty * 8 + 4];
                const ulonglong2 bb0 = *(const ulonglong2*)&Bs[buf][kk][tx * 8];
                const ulonglong2 bb1 = *(const ulonglong2*)&Bs[buf][kk][tx * 8 + 4];
                const float a[8] = {a0.x, a0.y, a0.z, a0.w,
                                    a1.x, a1.y, a1.z, a1.w};
#pragma unroll
                for (int i = 0; i < 8; ++i) {
                    const unsigned long long ad = pack2(a[i], a[i]);
                    FMA2(acc2[i][0], ad, bb0.x);
                    FMA2(acc2[i][1], ad, bb0.y);
                    FMA2(acc2[i][2], ad, bb1.x);
                    FMA2(acc2[i][3], ad, bb1.y);
                }
            }
        }
        if (c < 31) {                     // stage c+1 into the other buffer
            if (buf == 0) { STS_FRAG(1); } else { STS_FRAG(0); }
        }
    }
#undef STS_FRAG

    if (grpActive) {
        float* Gt = g_G + ((size_t)t << 18);     // 2048*128 = 1<<18
#pragma unroll
        for (int i = 0; i < 8; ++i) {
            float f0, f1, f2, f3, f4, f5, f6, f7;
            unpack2(acc2[i][0], f0, f1);
            unpack2(acc2[i][1], f2, f3);
            unpack2(acc2[i][2], f4, f5);
            unpack2(acc2[i][3], f6, f7);
            const size_t o = (size_t)(j0 + ty * 8 + i) * Bsz + tx * 8;
            *(float4*)&Gt[o]     = make_float4(f0, f1, f2, f3);
            *(float4*)&Gt[o + 4] = make_float4(f4, f5, f6, f7);
        }
    }
}

// =============================================================================
// Per-btile software barrier (32 blocks), release/acquire atomics.
// Single hot gen word: releaser's one store wakes all spinners (L2 broadcast)
// — measured BEST handoff (round 14); per-slot flag polling regressed (r15).
// =============================================================================
__device__ __forceinline__ void tile_barrier(unsigned* cnt, unsigned* gen)
{
    __syncthreads();
    if (threadIdx.x == 0) {
        const unsigned old = ld_relaxed_gpu(gen);
        const unsigned ticket = atom_add_acqrel_gpu(cnt, 1u);
        if (ticket == 31u) {
            st_relaxed_gpu(cnt, 0u);
            st_release_gpu(gen, old + 1u);
        } else {
            while (ld_acquire_gpu(gen) == old) { }
        }
    }
    __syncthreads();
}

__device__ __forceinline__ float sigmf(float x) {
    return __fdividef(1.f, 1.f + __expf(-x));
}
__device__ __forceinline__ float tanh_fast(float x) {
    return 1.f - __fdividef(2.f, __expf(2.f * x) + 1.f);
}

// =============================================================================
// Phase 2: persistent recurrence (round-14 structure, verbatim).
// 128 blocks = (btile 0..3 [32 rows]) x (ntile 0..31 [16 units]), 512 thr.
// =============================================================================
__global__ void __launch_bounds__(512, 1) lstm_steps_kernel(
    const float* __restrict__ Whh,
    const int*   __restrict__ lensraw,
    float* __restrict__ out,    // [B,T,H]
    float* __restrict__ hfin,   // [B,H]
    float* __restrict__ cfin)   // [B,H]
{
    extern __shared__ float sm[];
    float* W_s = sm;                       // [512][64]
    float* h_s = sm + 512 * 64;            // [512][32]
    float* P_s = sm + 512 * 64 + 512 * 32; // [4][32][PPITCH]

    const int tid   = threadIdx.x;
    const int bx    = blockIdx.x;
    const int ntile = bx & 31;
    const int btile = bx >> 5;
    const int n0    = ntile * 16;
    const int b0    = btile * 32;
    unsigned* bar_cnt = &g_bar_cnt4[btile][0];
    unsigned* bar_gen = &g_bar_gen4[btile][0];

    // ---- stage W_hh (once): W_s[k][nh*4+gate] = Whh[gate*512 + n0+nh][k]
    {
        const int c     = tid >> 3;
        const int chunk = tid & 7;
        const int gate  = c & 3;
        const int nh    = c >> 2;
        const float* wrow = Whh + (size_t)(gate * Hsz + n0 + nh) * Hsz;
        for (int k = chunk * 64; k < chunk * 64 + 64; k += 4) {
            const float4 v = *(const float4*)(wrow + k);
            W_s[(k + 0) * 64 + c] = v.x;
            W_s[(k + 1) * 64 + c] = v.y;
            W_s[(k + 2) * 64 + c] = v.z;
            W_s[(k + 3) * 64 + c] = v.w;
        }
    }
    // ---- zero this block's slice of hbuf[0]
    {
        const int r = tid >> 4, cc = tid & 15;
        g_hbuf[0][(size_t)(b0 + r) * Hsz + n0 + cc] = 0.f;
    }
    // ---- zero-fill out for this btile
    {
        const float4 z4 = make_float4(0.f, 0.f, 0.f, 0.f);
        for (int it = 0; it < 256; ++it) {
            const int idx = it * 512 + tid;
            const int bt  = idx >> 7;
            const int f4  = idx & 127;
            const int r   = bt >> 5;
            const int tt  = ntile * 32 + (bt & 31);
            float4* dst = (float4*)(out + ((size_t)(b0 + r) * Tsz + tt) * Hsz);
            dst[f4] = z4;
        }
    }
    tile_barrier(bar_cnt, bar_gen);

    // ---- GEMM mapping
    const int cg = tid & 31;
    const int rg = (tid >> 5) & 3;
    const int kq = tid >> 7;
    const float* wbase = W_s + 2 * cg;
    const float* hbase = h_s + rg * 8;
    float* Pk = P_s + kq * (32 * PPITCH);

    // ---- epilogue mapping: one (row, unit) per thread
    const int er = tid & 31;
    const int un = tid >> 5;
    const int eb = b0 + er;
    const int n  = n0 + un;

    const bool is64 = lens_is64(lensraw);
    const int len_tile = load_len(lensraw, is64, b0);
    const int len_r    = load_len(lensraw, is64, eb);

    float hprev = 0.f, creg = 0.f;

    const int st_b  = tid & 31;
    const int st_kc = tid >> 5;

#pragma unroll 1
    for (int t = 0; t < Tsz; ++t) {
        float* hnext = g_hbuf[(t + 1) & 1];
        const bool tileActive = (t < len_tile);

        if (tileActive) {
            // -- prefetch G[t] (coalesced: lanes = consecutive b)
            const float* grb = g_G + ((size_t)t << 18) + (size_t)n * Bsz + eb;
            const float gi = __ldcg(grb);
            const float gf = __ldcg(grb + 512 * Bsz);
            const float gg = __ldcg(grb + 1024 * Bsz);
            const float go = __ldcg(grb + 1536 * Bsz);

            // -- stage h tile: h_s[k][b]
            {
                const float* src = g_hbuf[t & 1] +
                                   (size_t)(b0 + st_b) * Hsz + st_kc * 32;
#pragma unroll
                for (int i = 0; i < 8; ++i) {
                    const float4 v = __ldcg((const float4*)(src + i * 4));
                    const int k = st_kc * 32 + i * 4;
                    h_s[(k + 0) * 32 + st_b] = v.x;
                    h_s[(k + 1) * 32 + st_b] = v.y;
                    h_s[(k + 2) * 32 + st_b] = v.z;
                    h_s[(k + 3) * 32 + st_b] = v.w;
                }
            }
            __syncthreads();

            // -- micro-GEMM over this thread's k quarter (8 rows x 2 cols)
            unsigned long long A00 = 0ull, A01 = 0ull;
            unsigned long long A10 = 0ull, A11 = 0ull;
            unsigned long long A20 = 0ull, A21 = 0ull;
            unsigned long long A30 = 0ull, A31 = 0ull;
            const int kend = kq * 128 + 128;
#pragma unroll 8
            for (int k = kq * 128; k < kend; ++k) {
                const float2 wv = *(const float2*)(wbase + k * 64);
                const ulonglong2 hA = *(const ulonglong2*)(hbase + k * 32);
                const ulonglong2 hB = *(const ulonglong2*)(hbase + k * 32 + 4);
                const unsigned long long w0 = pack2(wv.x, wv.x);
                const unsigned long long w1 = pack2(wv.y, wv.y);
                FMA2(A00, hA.x, w0); FMA2(A01, hA.x, w1);
                FMA2(A10, hA.y, w0); FMA2(A11, hA.y, w1);
                FMA2(A20, hB.x, w0); FMA2(A21, hB.x, w1);
                FMA2(A30, hB.y, w0); FMA2(A31, hB.y, w1);
            }
            {
                float e0, o0, e1, o1;
                const int rb = rg * 8;
                float2* pr;
                unpack2(A00, e0, o0); unpack2(A01, e1, o1);
                pr = (float2*)&Pk[(rb+0)*PPITCH + 2*cg]; *pr = make_float2(e0, e1);
                pr = (float2*)&Pk[(rb+1)*PPITCH + 2*cg]; *pr = make_float2(o0, o1);
                unpack2(A10, e0, o0); unpack2(A11, e1, o1);
                pr = (float2*)&Pk[(rb+2)*PPITCH + 2*cg]; *pr = make_float2(e0, e1);
                pr = (float2*)&Pk[(rb+3)*PPITCH + 2*cg]; *pr = make_float2(o0, o1);
                unpack2(A20, e0, o0); unpack2(A21, e1, o1);
                pr = (float2*)&Pk[(rb+4)*PPITCH + 2*cg]; *pr = make_float2(e0, e1);
                pr = (float2*)&Pk[(rb+5)*PPITCH + 2*cg]; *pr = make_float2(o0, o1);
                unpack2(A30, e0, o0); unpack2(A31, e1, o1);
                pr = (float2*)&Pk[(rb+6)*PPITCH + 2*cg]; *pr = make_float2(e0, e1);
                pr = (float2*)&Pk[(rb+7)*PPITCH + 2*cg]; *pr = make_float2(o0, o1);
            }
            __syncthreads();

            // -- epilogue: reduce 4 k-quarters, add G, LSTM update
            {
                const float4 p0 = *(const float4*)&P_s[0*32*PPITCH + er*PPITCH + un*4];
                const float4 p1 = *(const float4*)&P_s[1*32*PPITCH + er*PPITCH + un*4];
                const float4 p2 = *(const float4*)&P_s[2*32*PPITCH + er*PPITCH + un*4];
                const float4 p3 = *(const float4*)&P_s[3*32*PPITCH + er*PPITCH + un*4];
                const float ai = (p0.x + p1.x) + (p2.x + p3.x);
                const float af = (p0.y + p1.y) + (p2.y + p3.y);
                const float ag = (p0.z + p1.z) + (p2.z + p3.z);
                const float ao = (p0.w + p1.w) + (p2.w + p3.w);
                const float iv = sigmf(ai + gi);
                const float fv = sigmf(af + gf);
                const float gv = tanh_fast(ag + gg);
                const float ov = sigmf(ao + go);
                const float cn = fv * creg + iv * gv;
                const float hn = ov * tanh_fast(cn);
                const bool act = (t < len_r);
                creg  = act ? cn : creg;
                hprev = act ? hn : hprev;
                if (act) out[((size_t)eb * Tsz + t) * Hsz + n] = hn;
                hnext[(size_t)eb * Hsz + n] = hprev;
            }
        }
        tile_barrier(bar_cnt, bar_gen);   // h handoff within this btile
    }

    hfin[(size_t)eb * Hsz + n] = hprev;
    cfin[(size_t)eb * Hsz + n] = creg;
}

// ---------------------------------------------------------------------------
extern "C" void kernel_launch(void* const* d_in, const int* in_sizes, int n_in,
                              void* d_out, int out_size)
{
    (void)in_sizes; (void)n_in; (void)out_size;
    const float* seq  = (const float*)d_in[0];
    const int*   lens = (const int*)d_in[1];
    const float* Wih  = (const float*)d_in[2];
    const float* Whh  = (const float*)d_in[3];
    const float* bih  = (const float*)d_in[4];
    const float* bhh  = (const float*)d_in[5];

    float* outp = (float*)d_out;
    float* hfin = outp + (size_t)Bsz * Tsz * Hsz;
    float* cfin = hfin + (size_t)Bsz * Hsz;

    const int smem2 = (512 * 64 + 512 * 32 + 4 * 32 * PPITCH) * 4;
    cudaFuncSetAttribute(lstm_steps_kernel,
                         cudaFuncAttributeMaxDynamicSharedMemorySize, smem2);

    // Phase 1: input-gate GEMM (double-buffered) -> transposed G[t][j][b]
    dim3 grid1(G4 / 128, Tsz);
    pregemm_kernel<<<grid1, 256>>>(seq, Wih, bih, bhh, lens);

    // Phase 2: persistent recurrence (128 co-resident blocks, atomic barriers)
    lstm_steps_kernel<<<128, 512, smem2>>>(Whh, lens, outp, hfin, cfin);
}

// round 17
// speedup vs baseline: 1.6346x; 1.2408x over previous
#include <cuda_runtime.h>
#include <cstdint>
#include <math.h>

// ---------------------------------------------------------------------------
// Problem constants: B=128, T=1024, D=512, H=512, 4H=2048
//   0: sequence_tensor f32 [128,1024,512]
//   1: batch_lengths   int32 (JAX x64 off) or int64 [128], sorted descending
//   2: W_ih f32 [2048,512]   3: W_hh f32 [2048,512]
//   4: b_ih f32 [2048]       5: b_hh f32 [2048]
// Output: concat( out[128,1024,512], h_final[1,128,512], c_final[1,128,512] )
//
// NOTE: harness lowers PTX through compute_103 (non-'a') -> tcgen05 is
// UNAVAILABLE (ptxas rejects it).  FFMA2 roofline is the ceiling.
//
// Round-17: kill the three scattered memory ops in the recurrence step:
//   - g_hbuf now stored k-major [n][b]  -> staging LDG coalesced AND
//     epilogue hnext store coalesced (lanes = consecutive b)
//   - out store staged through smem (aliased onto h_s) and written by a
//     lane-remapped pass (lanes = consecutive n) -> 2x64B txn/warp vs 32
// Phase 1 (double-buffered FFMA2 SGEMM) and barrier unchanged from round 16.
// ---------------------------------------------------------------------------

#define Bsz   128
#define Tsz   1024
#define Dsz   512
#define Hsz   512
#define G4    2048
#define PPITCH 68

// G stored TRANSPOSED: G[t][j][b] (phase-1 stores / phase-2 prefetch coalesced)
__device__ float g_G[(size_t)Tsz * G4 * Bsz];
// Hidden state double buffer, K-MAJOR: g_hbuf[buf][n][b]
__device__ float g_hbuf[2][Hsz * Bsz];
__device__ __align__(128) unsigned g_bar_cnt4[4][32];
__device__ __align__(128) unsigned g_bar_gen4[4][32];

// ---- packed fp32 helpers (FFMA2 via PTX fma.rn.f32x2) -----------------------
__device__ __forceinline__ unsigned long long pack2(float x, float y) {
    unsigned long long r;
    asm("mov.b64 %0, {%1, %2};" : "=l"(r) : "f"(x), "f"(y));
    return r;
}
__device__ __forceinline__ void unpack2(unsigned long long v, float& x, float& y) {
    asm("mov.b64 {%0, %1}, %2;" : "=f"(x), "=f"(y) : "l"(v));
}
#define FMA2(d, a, b) asm("fma.rn.f32x2 %0, %1, %2, %0;" : "+l"(d) : "l"(a), "l"(b))

// ---- scoped atomics / release-acquire ----------------------------------------
__device__ __forceinline__ unsigned ld_acquire_gpu(unsigned* p) {
    unsigned v;
    asm volatile("ld.acquire.gpu.u32 %0, [%1];" : "=r"(v) : "l"(p) : "memory");
    return v;
}
__device__ __forceinline__ unsigned ld_relaxed_gpu(unsigned* p) {
    unsigned v;
    asm volatile("ld.relaxed.gpu.u32 %0, [%1];" : "=r"(v) : "l"(p) : "memory");
    return v;
}
__device__ __forceinline__ unsigned atom_add_acqrel_gpu(unsigned* p, unsigned v) {
    unsigned o;
    asm volatile("atom.add.acq_rel.gpu.u32 %0, [%1], %2;"
                 : "=r"(o) : "l"(p), "r"(v) : "memory");
    return o;
}
__device__ __forceinline__ void st_release_gpu(unsigned* p, unsigned v) {
    asm volatile("st.release.gpu.u32 [%0], %1;" :: "l"(p), "r"(v) : "memory");
}
__device__ __forceinline__ void st_relaxed_gpu(unsigned* p, unsigned v) {
    asm volatile("st.relaxed.gpu.u32 [%0], %1;" :: "l"(p), "r"(v) : "memory");
}

// ---- length dtype detection --------------------------------------------------
__device__ __forceinline__ bool lens_is64(const int* p) {
    return (p[1] == 0 && p[3] == 0 && p[5] == 0);
}
__device__ __forceinline__ int load_len(const int* p, bool is64, int b) {
    return is64 ? p[2 * b] : p[b];
}

// ---------------------------------------------------------------------------
// Phase 1: G[t][j][b] = sum_k W_ih[j][k] * seq[b][t][k] + bias[j]
// 128x128x16 SGEMM per block, FFMA2, double-buffered k-pipeline (round-15 win).
// ---------------------------------------------------------------------------
__global__ void __launch_bounds__(256) pregemm_kernel(
    const float* __restrict__ seq,
    const float* __restrict__ Wih,
    const float* __restrict__ bih,
    const float* __restrict__ bhh,
    const int*   __restrict__ lensraw)
{
    __shared__ float As[2][16][128];
    __shared__ float Bs[2][16][128];

    const int t   = blockIdx.y;
    const int j0  = blockIdx.x * 128;
    const int tid = threadIdx.x;
    const int tx  = tid & 15;            // batch col group (8 b)
    const int ty  = tid >> 4;            // gate row group (8 j)

    const bool is64 = lens_is64(lensraw);
    const bool grpActive = (load_len(lensraw, is64, tx * 8) > t);

    unsigned long long acc2[8][4];
#pragma unroll
    for (int i = 0; i < 8; ++i) {
        const int j = j0 + ty * 8 + i;
        const float bv = bih[j] + bhh[j];
        const unsigned long long bb = pack2(bv, bv);
#pragma unroll
        for (int p = 0; p < 4; ++p) acc2[i][p] = bb;
    }

    const int lm = tid >> 1;
    const int lk = (tid & 1) * 8;
    const float* arow = Wih + (size_t)(j0 + lm) * Dsz + lk;          // gates
    const float* brow = seq + ((size_t)lm * Tsz + t) * Dsz + lk;     // batch

    float4 fa0 = *(const float4*)(arow);
    float4 fa1 = *(const float4*)(arow + 4);
    float4 fb0 = *(const float4*)(brow);
    float4 fb1 = *(const float4*)(brow + 4);

#define STS_FRAG(B) do {                                                     \
    As[B][lk + 0][lm] = fa0.x; As[B][lk + 1][lm] = fa0.y;                    \
    As[B][lk + 2][lm] = fa0.z; As[B][lk + 3][lm] = fa0.w;                    \
    As[B][lk + 4][lm] = fa1.x; As[B][lk + 5][lm] = fa1.y;                    \
    As[B][lk + 6][lm] = fa1.z; As[B][lk + 7][lm] = fa1.w;                    \
    Bs[B][lk + 0][lm] = fb0.x; Bs[B][lk + 1][lm] = fb0.y;                    \
    Bs[B][lk + 2][lm] = fb0.z; Bs[B][lk + 3][lm] = fb0.w;                    \
    Bs[B][lk + 4][lm] = fb1.x; Bs[B][lk + 5][lm] = fb1.y;                    \
    Bs[B][lk + 6][lm] = fb1.z; Bs[B][lk + 7][lm] = fb1.w;                    \
} while (0)

    STS_FRAG(0);

#pragma unroll 1
    for (int c = 0; c < 32; ++c) {
        __syncthreads();
        const int buf = c & 1;
        if (c < 31) {
            const int k0 = (c + 1) * 16;
            fa0 = *(const float4*)(arow + k0);
            fa1 = *(const float4*)(arow + k0 + 4);
            fb0 = *(const float4*)(brow + k0);
            fb1 = *(const float4*)(brow + k0 + 4);
        }
        if (grpActive) {
#pragma unroll
            for (int kk = 0; kk < 16; ++kk) {
                const float4 a0 = *(const float4*)&As[buf][kk][ty * 8];
                const float4 a1 = *(const float4*)&As[buf][kk][ty * 8 + 4];
                const ulonglong2 bb0 = *(const ulonglong2*)&Bs[buf][kk][tx * 8];
                const ulonglong2 bb1 = *(const ulonglong2*)&Bs[buf][kk][tx * 8 + 4];
                const float a[8] = {a0.x, a0.y, a0.z, a0.w,
                                    a1.x, a1.y, a1.z, a1.w};
#pragma unroll
                for (int i = 0; i < 8; ++i) {
                    const unsigned long long ad = pack2(a[i], a[i]);
                    FMA2(acc2[i][0], ad, bb0.x);
                    FMA2(acc2[i][1], ad, bb0.y);
                    FMA2(acc2[i][2], ad, bb1.x);
                    FMA2(acc2[i][3], ad, bb1.y);
                }
            }
        }
        if (c < 31) {
            if (buf == 0) { STS_FRAG(1); } else { STS_FRAG(0); }
        }
    }
#undef STS_FRAG

    if (grpActive) {
        float* Gt = g_G + ((size_t)t << 18);     // 2048*128 = 1<<18
#pragma unroll
        for (int i = 0; i < 8; ++i) {
            float f0, f1, f2, f3, f4, f5, f6, f7;
            unpack2(acc2[i][0], f0, f1);
            unpack2(acc2[i][1], f2, f3);
            unpack2(acc2[i][2], f4, f5);
            unpack2(acc2[i][3], f6, f7);
            const size_t o = (size_t)(j0 + ty * 8 + i) * Bsz + tx * 8;
            *(float4*)&Gt[o]     = make_float4(f0, f1, f2, f3);
            *(float4*)&Gt[o + 4] = make_float4(f4, f5, f6, f7);
        }
    }
}

// =============================================================================
// Per-btile software barrier (32 blocks), release/acquire atomics.
// Single hot gen word (measured best handoff; per-slot flags regressed r15).
// =============================================================================
__device__ __forceinline__ void tile_barrier(unsigned* cnt, unsigned* gen)
{
    __syncthreads();
    if (threadIdx.x == 0) {
        const unsigned old = ld_relaxed_gpu(gen);
        const unsigned ticket = atom_add_acqrel_gpu(cnt, 1u);
        if (ticket == 31u) {
            st_relaxed_gpu(cnt, 0u);
            st_release_gpu(gen, old + 1u);
        } else {
            while (ld_acquire_gpu(gen) == old) { }
        }
    }
    __syncthreads();
}

__device__ __forceinline__ float sigmf(float x) {
    return __fdividef(1.f, 1.f + __expf(-x));
}
__device__ __forceinline__ float tanh_fast(float x) {
    return 1.f - __fdividef(2.f, __expf(2.f * x) + 1.f);
}

// =============================================================================
// Phase 2: persistent recurrence.
// 128 blocks = (btile 0..3 [32 rows]) x (ntile 0..31 [16 units]), 512 thr.
// g_hbuf is k-major [n][b]: staging LDG coalesced, hnext store coalesced.
// out staged through smem (os aliases h_s; safe between the P-sync and the
// next tile_barrier) and written with lanes = consecutive n.
// =============================================================================
__global__ void __launch_bounds__(512, 1) lstm_steps_kernel(
    const float* __restrict__ Whh,
    const int*   __restrict__ lensraw,
    float* __restrict__ out,    // [B,T,H]
    float* __restrict__ hfin,   // [B,H]
    float* __restrict__ cfin)   // [B,H]
{
    extern __shared__ float sm[];
    float* W_s = sm;                       // [512][64]
    float* h_s = sm + 512 * 64;            // [512][32]
    float* P_s = sm + 512 * 64 + 512 * 32; // [4][32][PPITCH]
    float* os  = h_s;                      // out-stage alias [32][17]

    const int tid   = threadIdx.x;
    const int bx    = blockIdx.x;
    const int ntile = bx & 31;
    const int btile = bx >> 5;
    const int n0    = ntile * 16;
    const int b0    = btile * 32;
    unsigned* bar_cnt = &g_bar_cnt4[btile][0];
    unsigned* bar_gen = &g_bar_gen4[btile][0];

    // ---- stage W_hh (once): W_s[k][nh*4+gate] = Whh[gate*512 + n0+nh][k]
    {
        const int c     = tid >> 3;
        const int chunk = tid & 7;
        const int gate  = c & 3;
        const int nh    = c >> 2;
        const float* wrow = Whh + (size_t)(gate * Hsz + n0 + nh) * Hsz;
        for (int k = chunk * 64; k < chunk * 64 + 64; k += 4) {
            const float4 v = *(const float4*)(wrow + k);
            W_s[(k + 0) * 64 + c] = v.x;
            W_s[(k + 1) * 64 + c] = v.y;
            W_s[(k + 2) * 64 + c] = v.z;
            W_s[(k + 3) * 64 + c] = v.w;
        }
    }
    // ---- zero this block's slice of hbuf[0]  (k-major: [n0..n0+16)[b0..b0+32))
    {
        const int nn = tid >> 5;            // 0..15
        const int bb = tid & 31;
        g_hbuf[0][(size_t)(n0 + nn) * Bsz + b0 + bb] = 0.f;
    }
    // ---- zero-fill out for this btile
    {
        const float4 z4 = make_float4(0.f, 0.f, 0.f, 0.f);
        for (int it = 0; it < 256; ++it) {
            const int idx = it * 512 + tid;
            const int bt  = idx >> 7;
            const int f4  = idx & 127;
            const int r   = bt >> 5;
            const int tt  = ntile * 32 + (bt & 31);
            float4* dst = (float4*)(out + ((size_t)(b0 + r) * Tsz + tt) * Hsz);
            dst[f4] = z4;
        }
    }
    tile_barrier(bar_cnt, bar_gen);

    // ---- GEMM mapping
    const int cg = tid & 31;
    const int rg = (tid >> 5) & 3;
    const int kq = tid >> 7;
    const float* wbase = W_s + 2 * cg;
    const float* hbase = h_s + rg * 8;
    float* Pk = P_s + kq * (32 * PPITCH);

    // ---- epilogue mapping: one (row, unit) per thread, lanes = b
    const int er = tid & 31;
    const int un = tid >> 5;
    const int eb = b0 + er;
    const int n  = n0 + un;

    // ---- out-writer mapping: lanes = consecutive n
    const int wr = tid >> 4;                // row 0..31
    const int wu = tid & 15;                // unit 0..15

    const bool is64 = lens_is64(lensraw);
    const int len_tile = load_len(lensraw, is64, b0);
    const int len_r    = load_len(lensraw, is64, eb);
    const int len_w    = load_len(lensraw, is64, b0 + wr);

    float hprev = 0.f, creg = 0.f;

#pragma unroll 1
    for (int t = 0; t < Tsz; ++t) {
        float* hnext = g_hbuf[(t + 1) & 1];
        const bool tileActive = (t < len_tile);

        if (tileActive) {
            // -- prefetch G[t] (coalesced: lanes = consecutive b)
            const float* grb = g_G + ((size_t)t << 18) + (size_t)n * Bsz + eb;
            const float gi = __ldcg(grb);
            const float gf = __ldcg(grb + 512 * Bsz);
            const float gg = __ldcg(grb + 1024 * Bsz);
            const float go = __ldcg(grb + 1536 * Bsz);

            // -- stage h tile: global [k][b0..b0+32) -> h_s[k][b], coalesced
            {
                const float4* hsrc4 =
                    (const float4*)(g_hbuf[t & 1]) + (b0 >> 2);
#pragma unroll
                for (int i = 0; i < 8; ++i) {
                    const int idx = tid + i * 512;   // 0..4095 float4 slots
                    const int k   = idx >> 3;        // 0..511
                    const int f4  = idx & 7;         // 0..7 (b chunk)
                    const float4 v = __ldcg(hsrc4 + (size_t)k * 32 + f4);
                    *(float4*)&h_s[k * 32 + f4 * 4] = v;
                }
            }
            __syncthreads();

            // -- micro-GEMM over this thread's k quarter (8 rows x 2 cols)
            unsigned long long A00 = 0ull, A01 = 0ull;
            unsigned long long A10 = 0ull, A11 = 0ull;
            unsigned long long A20 = 0ull, A21 = 0ull;
            unsigned long long A30 = 0ull, A31 = 0ull;
            const int kend = kq * 128 + 128;
#pragma unroll 8
            for (int k = kq * 128; k < kend; ++k) {
                const float2 wv = *(const float2*)(wbase + k * 64);
                const ulonglong2 hA = *(const ulonglong2*)(hbase + k * 32);
                const ulonglong2 hB = *(const ulonglong2*)(hbase + k * 32 + 4);
                const unsigned long long w0 = pack2(wv.x, wv.x);
                const unsigned long long w1 = pack2(wv.y, wv.y);
                FMA2(A00, hA.x, w0); FMA2(A01, hA.x, w1);
                FMA2(A10, hA.y, w0); FMA2(A11, hA.y, w1);
                FMA2(A20, hB.x, w0); FMA2(A21, hB.x, w1);
                FMA2(A30, hB.y, w0); FMA2(A31, hB.y, w1);
            }
            {
                float e0, o0, e1, o1;
                const int rb = rg * 8;
                float2* pr;
                unpack2(A00, e0, o0); unpack2(A01, e1, o1);
                pr = (float2*)&Pk[(rb+0)*PPITCH + 2*cg]; *pr = make_float2(e0, e1);
                pr = (float2*)&Pk[(rb+1)*PPITCH + 2*cg]; *pr = make_float2(o0, o1);
                unpack2(A10, e0, o0); unpack2(A11, e1, o1);
                pr = (float2*)&Pk[(rb+2)*PPITCH + 2*cg]; *pr = make_float2(e0, e1);
                pr = (float2*)&Pk[(rb+3)*PPITCH + 2*cg]; *pr = make_float2(o0, o1);
                unpack2(A20, e0, o0); unpack2(A21, e1, o1);
                pr = (float2*)&Pk[(rb+4)*PPITCH + 2*cg]; *pr = make_float2(e0, e1);
                pr = (float2*)&Pk[(rb+5)*PPITCH + 2*cg]; *pr = make_float2(o0, o1);
                unpack2(A30, e0, o0); unpack2(A31, e1, o1);
                pr = (float2*)&Pk[(rb+6)*PPITCH + 2*cg]; *pr = make_float2(e0, e1);
                pr = (float2*)&Pk[(rb+7)*PPITCH + 2*cg]; *pr = make_float2(o0, o1);
            }
            __syncthreads();   // P_s ready; ALSO: all h_s reads done -> os safe

            // -- epilogue: reduce 4 k-quarters, add G, LSTM update
            {
                const float4 p0 = *(const float4*)&P_s[0*32*PPITCH + er*PPITCH + un*4];
                const float4 p1 = *(const float4*)&P_s[1*32*PPITCH + er*PPITCH + un*4];
                const float4 p2 = *(const float4*)&P_s[2*32*PPITCH + er*PPITCH + un*4];
                const float4 p3 = *(const float4*)&P_s[3*32*PPITCH + er*PPITCH + un*4];
                const float ai = (p0.x + p1.x) + (p2.x + p3.x);
                const float af = (p0.y + p1.y) + (p2.y + p3.y);
                const float ag = (p0.z + p1.z) + (p2.z + p3.z);
                const float ao = (p0.w + p1.w) + (p2.w + p3.w);
                const float iv = sigmf(ai + gi);
                const float fv = sigmf(af + gf);
                const float gv = tanh_fast(ag + gg);
                const float ov = sigmf(ao + go);
                const float cn = fv * creg + iv * gv;
                const float hn = ov * tanh_fast(cn);
                const bool act = (t < len_r);
                creg  = act ? cn : creg;
                hprev = act ? hn : hprev;
                // coalesced hnext store (k-major hbuf, lanes = consecutive b)
                hnext[(size_t)n * Bsz + eb] = hprev;
                // stage out value for the lane-remapped writer
                os[er * 17 + un] = hn;
            }
            __syncthreads();

            // -- out writer: lanes = consecutive n -> 2 x 64B per warp
            if (t < len_w)
                out[((size_t)(b0 + wr) * Tsz + t) * Hsz + n0 + wu] =
                    os[wr * 17 + wu];
        }
        // inactive tile: outputs already zero-filled, h frozen

        tile_barrier(bar_cnt, bar_gen);   // h handoff within this btile
    }

    hfin[(size_t)eb * Hsz + n] = hprev;
    cfin[(size_t)eb * Hsz + n] = creg;
}

// ---------------------------------------------------------------------------
extern "C" void kernel_launch(void* const* d_in, const int* in_sizes, int n_in,
                              void* d_out, int out_size)
{
    (void)in_sizes; (void)n_in; (void)out_size;
    const float* seq  = (const float*)d_in[0];
    const int*   lens = (const int*)d_in[1];
    const float* Wih  = (const float*)d_in[2];
    const float* Whh  = (const float*)d_in[3];
    const float* bih  = (const float*)d_in[4];
    const float* bhh  = (const float*)d_in[5];

    float* outp = (float*)d_out;
    float* hfin = outp + (size_t)Bsz * Tsz * Hsz;
    float* cfin = hfin + (size_t)Bsz * Hsz;

    const int smem2 = (512 * 64 + 512 * 32 + 4 * 32 * PPITCH) * 4;
    cudaFuncSetAttribute(lstm_steps_kernel,
                         cudaFuncAttributeMaxDynamicSharedMemorySize, smem2);

    // Phase 1: input-gate GEMM (double-buffered) -> transposed G[t][j][b]
    dim3 grid1(G4 / 128, Tsz);
    pregemm_kernel<<<grid1, 256>>>(seq, Wih, bih, bhh, lens);

    // Phase 2: persistent recurrence (128 co-resident blocks, atomic barriers)
    lstm_steps_kernel<<<128, 512, smem2>>>(Whh, lens, outp, hfin, cfin);
}